// round 1
// baseline (speedup 1.0000x reference)
#include <cuda_runtime.h>
#include <math.h>

// BezierRenderer: 16 batches, 512x512 output, 10 segments per batch.
// Tile = 64 (x) x 16 (y) pixels. 256 threads/block, 4 px (float4) per thread.
// gridDim = (8, 32, 16)  -> (tiles_x, tiles_y, batch)

#define NSEG 10
#define SIZEI 512

__global__ void __launch_bounds__(256, 2)
bezier_kernel(const float* __restrict__ traj,
              const float* __restrict__ thk,
              float* __restrict__ out)
{
    __shared__ float s_pts_y[NSEG + 1], s_pts_x[NSEG + 1];
    __shared__ float s_vy[NSEG], s_vx[NSEG], s_dy[NSEG], s_dx[NSEG], s_id2[NSEG];
    __shared__ float s_thick, s_invthick;
    __shared__ int s_skip;

    const int b   = blockIdx.z;
    const int tid = threadIdx.x;

    // ---- stroke points (11) ----
    if (tid < NSEG + 1) {
        float py, px;
        if (tid < NSEG) {
            const int start[4] = {10, 6, 3, 0};
            float sy = 0.f, sx = 0.f;
#pragma unroll
            for (int i = 0; i < 4; i++) {
                float n = (float)(start[i] + tid) - 9.5f;
                float w = 0.75f * expf(-0.125f * n * n);   // exp(-0.5*(n/2)^2)
                sy += traj[b * 8 + i]     * w;             // c = 0 (y)
                sx += traj[b * 8 + 4 + i] * w;             // c = 1 (x)
            }
            py = sy * 512.f;
            px = sx * 512.f;
        } else {
            py = traj[b * 8 + 3] * 512.f;
            px = traj[b * 8 + 7] * 512.f;
        }
        s_pts_y[tid] = py;
        s_pts_x[tid] = px;
    }
    if (tid == 0) {
        float th = 0.f;
#pragma unroll
        for (int k = 0; k < 4; k++) th += thk[b * 4 + k] * 2.f + 0.5f;
        float t2 = 2.f * th;
        s_thick = t2;
        s_invthick = 1.f / t2;
    }
    __syncthreads();

    // ---- segment params ----
    if (tid < NSEG) {
        float vy = s_pts_y[tid], vx = s_pts_x[tid];
        float dy = s_pts_y[tid + 1] - vy;
        float dx = s_pts_x[tid + 1] - vx;
        s_vy[tid] = vy; s_vx[tid] = vx;
        s_dy[tid] = dy; s_dx[tid] = dx;
        s_id2[tid] = 1.f / (dy * dy + dx * dx + 1e-5f);
    }
    __syncthreads();

    // ---- tile cull: dist(pixel,seg) >= dist(center,seg) - 32.5 ----
    const int tile_x0 = blockIdx.x * 64;
    const int tile_y0 = blockIdx.y * 16;
    if (tid == 0) {
        float cx = (float)tile_x0 + 31.5f;
        float cy = (float)tile_y0 + 7.5f;
        float lim = s_thick + 33.0f;          // thick + half-diagonal + margin
        float lim2 = lim * lim;
        int skip = 1;
#pragma unroll
        for (int j = 0; j < NSEG; j++) {
            float ay = cy - s_vy[j];
            float ax = cx - s_vx[j];
            float dot = ay * s_dy[j] + ax * s_dx[j];
            float t = fminf(fmaxf(dot * s_id2[j], 0.f), 1.f);
            float ry = fmaf(-t, s_dy[j], ay);
            float rx = fmaf(-t, s_dx[j], ax);
            float dd = ry * ry + rx * rx;
            if (dd < lim2) skip = 0;
        }
        s_skip = skip;
    }
    __syncthreads();

    // thread -> pixels: 16 threads per row (4 px each), 16 rows
    const int row = tid >> 4;               // 0..15
    const int x   = tile_x0 + (tid & 15) * 4;
    const int y   = tile_y0 + row;
    float* outp = out + (size_t)b * (SIZEI * SIZEI) + (size_t)y * SIZEI + x;

    if (s_skip) {
        *reinterpret_cast<float4*>(outp) = make_float4(0.f, 0.f, 0.f, 0.f);
        return;
    }

    // load segment params into registers
    float vy[NSEG], vx[NSEG], dy[NSEG], dx[NSEG], id2[NSEG];
#pragma unroll
    for (int j = 0; j < NSEG; j++) {
        vy[j] = s_vy[j]; vx[j] = s_vx[j];
        dy[j] = s_dy[j]; dx[j] = s_dx[j];
        id2[j] = s_id2[j];
    }
    const float thick = s_thick;
    const float invthick = s_invthick;

    const float yf = (float)y;
    const float x0 = (float)x;

    float m0 = 1e30f, m1 = 1e30f, m2 = 1e30f, m3 = 1e30f;

#pragma unroll
    for (int j = 0; j < NSEG; j++) {
        const float ay  = yf - vy[j];       // same for all 4 pixels (same row)
        const float cyd = ay * dy[j];
        const float djy = dy[j], djx = dx[j], vjx = vx[j], ij = id2[j];

        {
            float pvx = x0 - vjx;
            float dot = fmaf(pvx, djx, cyd);
            float t   = fminf(fmaxf(dot * ij, 0.f), 1.f);
            float ry  = fmaf(-t, djy, ay);
            float rx  = fmaf(-t, djx, pvx);
            m0 = fminf(m0, fmaf(ry, ry, rx * rx));
        }
        {
            float pvx = x0 + 1.f - vjx;
            float dot = fmaf(pvx, djx, cyd);
            float t   = fminf(fmaxf(dot * ij, 0.f), 1.f);
            float ry  = fmaf(-t, djy, ay);
            float rx  = fmaf(-t, djx, pvx);
            m1 = fminf(m1, fmaf(ry, ry, rx * rx));
        }
        {
            float pvx = x0 + 2.f - vjx;
            float dot = fmaf(pvx, djx, cyd);
            float t   = fminf(fmaxf(dot * ij, 0.f), 1.f);
            float ry  = fmaf(-t, djy, ay);
            float rx  = fmaf(-t, djx, pvx);
            m2 = fminf(m2, fmaf(ry, ry, rx * rx));
        }
        {
            float pvx = x0 + 3.f - vjx;
            float dot = fmaf(pvx, djx, cyd);
            float t   = fminf(fmaxf(dot * ij, 0.f), 1.f);
            float ry  = fmaf(-t, djy, ay);
            float rx  = fmaf(-t, djx, pvx);
            m3 = fminf(m3, fmaf(ry, ry, rx * rx));
        }
    }

    float4 res;
    res.x = fminf(fmaxf((thick - sqrtf(m0)) * invthick, 0.f), 1.f);
    res.y = fminf(fmaxf((thick - sqrtf(m1)) * invthick, 0.f), 1.f);
    res.z = fminf(fmaxf((thick - sqrtf(m2)) * invthick, 0.f), 1.f);
    res.w = fminf(fmaxf((thick - sqrtf(m3)) * invthick, 0.f), 1.f);

    *reinterpret_cast<float4*>(outp) = res;
}

extern "C" void kernel_launch(void* const* d_in, const int* in_sizes, int n_in,
                              void* d_out, int out_size)
{
    const float* traj = (const float*)d_in[0];   // (16, 2, 4)
    const float* thk  = (const float*)d_in[1];   // (16, 1, 4)
    float* out = (float*)d_out;                  // (16, 512, 512)

    dim3 grid(512 / 64, 512 / 16, 16);           // (8, 32, 16)
    bezier_kernel<<<grid, 256>>>(traj, thk, out);
}

// round 4
// speedup vs baseline: 1.7160x; 1.7160x over previous
#include <cuda_runtime.h>
#include <math.h>

// BezierRenderer: 16 batches, 512x512, 10 segments.
// Two kernels:
//  1) setup_kernel <<<16, 256>>>: per-batch segment params + per-tile segment masks
//  2) render_kernel <<<(8,32,16), 256>>>: barrier-free, mask-driven per-tile render
// Tile = 64 (x) x 16 (y). 256 threads/block, 4 px (float4) per thread.

#define NSEG    10
#define NBATCH  16
#define TILES_X 8
#define TILES_Y 32
#define TILES_PER_BATCH (TILES_X * TILES_Y)   // 256
#define NTILES  (TILES_PER_BATCH * NBATCH)    // 4096
#define SIZEI   512

struct SegParams {
    float4 seg[NSEG];        // {vy, vx, dy, dx}
    float  id2[NSEG];
    float  thick, invthick;
};

__device__ SegParams g_params[NBATCH];
__device__ unsigned int g_mask[NTILES];

// ---------------------------------------------------------------------------
// Setup: one block per batch. Computes stroke points, segment params, thickness,
// then every thread computes the segment mask for one tile of this batch.
// ---------------------------------------------------------------------------
__global__ void __launch_bounds__(256)
setup_kernel(const float* __restrict__ traj,
             const float* __restrict__ thk)
{
    __shared__ float s_py[NSEG + 1], s_px[NSEG + 1];
    __shared__ float s_vy[NSEG], s_vx[NSEG], s_dy[NSEG], s_dx[NSEG], s_id2[NSEG];
    __shared__ float s_thick;

    const int b   = blockIdx.x;
    const int tid = threadIdx.x;

    if (tid <= NSEG) {
        float sy, sx;
        if (tid < NSEG) {
            const int start[4] = {10, 6, 3, 0};
            sy = 0.f; sx = 0.f;
#pragma unroll
            for (int i = 0; i < 4; i++) {
                float n = (float)(start[i] + tid) - 9.5f;
                float w = 0.75f * expf(-0.125f * n * n);   // exp(-0.5*(n/2)^2)
                sy += traj[b * 8 + i]     * w;             // c = 0 (y)
                sx += traj[b * 8 + 4 + i] * w;             // c = 1 (x)
            }
        } else {
            sy = traj[b * 8 + 3];
            sx = traj[b * 8 + 7];
        }
        s_py[tid] = sy * 512.f;
        s_px[tid] = sx * 512.f;
    }
    if (tid == 0) {
        float th = 0.f;
#pragma unroll
        for (int k = 0; k < 4; k++) th += thk[b * 4 + k] * 2.f + 0.5f;
        float t2 = 2.f * th;
        s_thick = t2;
        g_params[b].thick    = t2;
        g_params[b].invthick = 1.f / t2;
    }
    __syncthreads();

    if (tid < NSEG) {
        float vy = s_py[tid], vx = s_px[tid];
        float dy = s_py[tid + 1] - vy;
        float dx = s_px[tid + 1] - vx;
        float id2 = 1.f / (dy * dy + dx * dx + 1e-5f);
        s_vy[tid] = vy;  s_vx[tid] = vx;
        s_dy[tid] = dy;  s_dx[tid] = dx;
        s_id2[tid] = id2;
        g_params[b].seg[tid] = make_float4(vy, vx, dy, dx);
        g_params[b].id2[tid] = id2;
    }
    __syncthreads();

    // One tile per thread: tile (tx, ty) = (tid & 7, tid >> 3)
    // Tile center: (tx*64 + 31.5, ty*16 + 7.5). Max pixel-to-center distance:
    // sqrt(31.5^2 + 7.5^2) = 32.38 < 33. Segment contributes only if
    // dist(center, seg) < thick + 33.
    const float cx = (float)((tid & 7) << 6) + 31.5f;
    const float cy = (float)((tid >> 3) << 4) + 7.5f;
    const float lim = s_thick + 33.0f;
    const float lim2 = lim * lim;

    unsigned int m = 0;
#pragma unroll
    for (int j = 0; j < NSEG; j++) {
        float ay = cy - s_vy[j];
        float ax = cx - s_vx[j];
        float dot = ay * s_dy[j] + ax * s_dx[j];
        float t = fminf(fmaxf(dot * s_id2[j], 0.f), 1.f);
        float ry = fmaf(-t, s_dy[j], ay);
        float rx = fmaf(-t, s_dx[j], ax);
        if (fmaf(ry, ry, rx * rx) < lim2) m |= (1u << j);
    }
    g_mask[b * TILES_PER_BATCH + tid] = m;
}

// ---------------------------------------------------------------------------
// Render: barrier-free. One tile per block; mask is uniform across the block
// so all branches are non-divergent.
// ---------------------------------------------------------------------------
__global__ void __launch_bounds__(256)
render_kernel(float* __restrict__ out)
{
    const int b   = blockIdx.z;
    const int tid = threadIdx.x;
    const int tile_id = b * TILES_PER_BATCH + blockIdx.y * TILES_X + blockIdx.x;

    const int x = (blockIdx.x << 6) + (tid & 15) * 4;
    const int y = (blockIdx.y << 4) + (tid >> 4);
    float* outp = out + ((size_t)b << 18) + ((size_t)y << 9) + x;

    unsigned int mask = __ldg(&g_mask[tile_id]);          // uniform across block
    if (mask == 0) {
        *reinterpret_cast<float4*>(outp) = make_float4(0.f, 0.f, 0.f, 0.f);
        return;
    }

    const SegParams* sp = &g_params[b];
    const float thick    = __ldg(&sp->thick);
    const float invthick = __ldg(&sp->invthick);

    const float yf = (float)y;
    const float x0 = (float)x;

    float m0 = 1e30f, m1 = 1e30f, m2 = 1e30f, m3 = 1e30f;

    while (mask) {
        const int j = __ffs(mask) - 1;
        mask &= mask - 1;

        const float4 s  = __ldg(&sp->seg[j]);   // {vy, vx, dy, dx}
        const float ij  = __ldg(&sp->id2[j]);
        const float vjx = s.y, djy = s.z, djx = s.w;

        const float ay  = yf - s.x;            // same for all 4 px (same row)
        const float cyd = ay * djy;

        {
            float pvx = x0 - vjx;
            float dot = fmaf(pvx, djx, cyd);
            float t   = fminf(fmaxf(dot * ij, 0.f), 1.f);
            float ry  = fmaf(-t, djy, ay);
            float rx  = fmaf(-t, djx, pvx);
            m0 = fminf(m0, fmaf(ry, ry, rx * rx));
        }
        {
            float pvx = x0 + 1.f - vjx;
            float dot = fmaf(pvx, djx, cyd);
            float t   = fminf(fmaxf(dot * ij, 0.f), 1.f);
            float ry  = fmaf(-t, djy, ay);
            float rx  = fmaf(-t, djx, pvx);
            m1 = fminf(m1, fmaf(ry, ry, rx * rx));
        }
        {
            float pvx = x0 + 2.f - vjx;
            float dot = fmaf(pvx, djx, cyd);
            float t   = fminf(fmaxf(dot * ij, 0.f), 1.f);
            float ry  = fmaf(-t, djy, ay);
            float rx  = fmaf(-t, djx, pvx);
            m2 = fminf(m2, fmaf(ry, ry, rx * rx));
        }
        {
            float pvx = x0 + 3.f - vjx;
            float dot = fmaf(pvx, djx, cyd);
            float t   = fminf(fmaxf(dot * ij, 0.f), 1.f);
            float ry  = fmaf(-t, djy, ay);
            float rx  = fmaf(-t, djx, pvx);
            m3 = fminf(m3, fmaf(ry, ry, rx * rx));
        }
    }

    float4 res;
    res.x = fminf(fmaxf((thick - sqrtf(m0)) * invthick, 0.f), 1.f);
    res.y = fminf(fmaxf((thick - sqrtf(m1)) * invthick, 0.f), 1.f);
    res.z = fminf(fmaxf((thick - sqrtf(m2)) * invthick, 0.f), 1.f);
    res.w = fminf(fmaxf((thick - sqrtf(m3)) * invthick, 0.f), 1.f);

    *reinterpret_cast<float4*>(outp) = res;
}

extern "C" void kernel_launch(void* const* d_in, const int* in_sizes, int n_in,
                              void* d_out, int out_size)
{
    const float* traj = (const float*)d_in[0];   // (16, 2, 4)
    const float* thk  = (const float*)d_in[1];   // (16, 1, 4)
    float* out = (float*)d_out;                  // (16, 512, 512)

    setup_kernel<<<NBATCH, 256>>>(traj, thk);

    dim3 grid(TILES_X, TILES_Y, NBATCH);         // (8, 32, 16)
    render_kernel<<<grid, 256>>>(out);
}